// round 4
// baseline (speedup 1.0000x reference)
#include <cuda_runtime.h>
#include <cstdint>

#define B_ 8
#define T_ 2048
#define C_ 1024
#define H_ 64
#define M_ (B_*T_)   // 16384

__device__ float g_q[M_*H_];
__device__ float g_k[M_*H_];
__device__ float g_v[M_*H_];
// split-K attention partials: [split][row][h] and [split][row][{m,l}]
__device__ float g_po[2*M_*H_];
__device__ float g_ml[2*M_*2];

__device__ __forceinline__ float tf32r(float x){
    asm("cvt.rna.tf32.f32 %0, %0;" : "+f"(x));
    return x;
}
__device__ __forceinline__ float4 tf32r4(float4 v){
    v.x=tf32r(v.x); v.y=tf32r(v.y); v.z=tf32r(v.z); v.w=tf32r(v.w);
    return v;
}

__device__ __forceinline__ void mma_tf32(float* d, const float* a, const float* b, const float* c){
    asm volatile("mma.sync.aligned.m16n8k8.row.col.f32.tf32.tf32.f32 "
        "{%0,%1,%2,%3}, {%4,%5,%6,%7}, {%8,%9}, {%10,%11,%12,%13};"
        : "=f"(d[0]),"=f"(d[1]),"=f"(d[2]),"=f"(d[3])
        : "r"(__float_as_uint(a[0])),"r"(__float_as_uint(a[1])),
          "r"(__float_as_uint(a[2])),"r"(__float_as_uint(a[3])),
          "r"(__float_as_uint(b[0])),"r"(__float_as_uint(b[1])),
          "f"(c[0]),"f"(c[1]),"f"(c[2]),"f"(c[3]));
}

// ---------------------------------------------------------------------------
// Fused QKV projection, tf32 mma, double-buffered register-staged pipeline.
// BM=64, BN=192, BK=32. 8 warps (4x2), warp tile 16x96. Grid = 256 CTAs
// (all resident, 2 CTAs/SM so barrier stalls overlap across CTAs).
// ---------------------------------------------------------------------------
#define AS_STRIDE 36   // ≡4 mod 32
#define BS_STRIDE 200  // ≡8 mod 32
#define QKV_SMEM ((2*64*AS_STRIDE + 2*32*BS_STRIDE)*4)

__global__ __launch_bounds__(256) void qkv_kernel(
    const float* __restrict__ x, const float* __restrict__ wq,
    const float* __restrict__ wk, const float* __restrict__ wv)
{
    extern __shared__ float sm[];
    float* Asm = sm;                       // 2 x 64*AS_STRIDE
    float* Bsm = sm + 2*64*AS_STRIDE;      // 2 x 32*BS_STRIDE

    const int tid  = threadIdx.x;
    const int lane = tid & 31, warp = tid >> 5;
    const int wm = warp & 3, wn = warp >> 2;
    const int g = lane >> 2, q = lane & 3;
    const int m0 = blockIdx.x * 64;

    float acc[12][4];
    #pragma unroll
    for (int j=0;j<12;j++){acc[j][0]=acc[j][1]=acc[j][2]=acc[j][3]=0.f;}

    float4 xs[2], ws[3][2];

#define QKV_LOAD(K0) do { \
    _Pragma("unroll") \
    for (int it=0; it<2; it++){ \
        int i = tid + it*256; int r = i>>3, c4 = (i&7)*4; \
        xs[it] = *(const float4*)&x[(size_t)(m0+r)*C_ + (K0) + c4]; \
    } \
    _Pragma("unroll") \
    for (int it=0; it<2; it++){ \
        int i = tid + it*256; int r = i>>4, c4 = (i&15)*4; \
        int gi = ((K0)+r)*H_ + c4; \
        ws[0][it] = *(const float4*)&wq[gi]; \
        ws[1][it] = *(const float4*)&wk[gi]; \
        ws[2][it] = *(const float4*)&wv[gi]; \
    } } while(0)

#define QKV_STORE(BUF) do { \
    float* A  = Asm + (BUF)*64*AS_STRIDE; \
    float* Bb = Bsm + (BUF)*32*BS_STRIDE; \
    _Pragma("unroll") \
    for (int it=0; it<2; it++){ \
        int i = tid + it*256; int r = i>>3, c4 = (i&7)*4; \
        *(float4*)&A[r*AS_STRIDE + c4] = tf32r4(xs[it]); \
    } \
    _Pragma("unroll") \
    for (int it=0; it<2; it++){ \
        int i = tid + it*256; int r = i>>4, c4 = (i&15)*4; \
        *(float4*)&Bb[r*BS_STRIDE + c4]       = tf32r4(ws[0][it]); \
        *(float4*)&Bb[r*BS_STRIDE + 64 + c4]  = tf32r4(ws[1][it]); \
        *(float4*)&Bb[r*BS_STRIDE + 128 + c4] = tf32r4(ws[2][it]); \
    } } while(0)

#define QKV_COMPUTE(BUF) do { \
    const float* A  = Asm + (BUF)*64*AS_STRIDE; \
    const float* Bb = Bsm + (BUF)*32*BS_STRIDE; \
    _Pragma("unroll") \
    for (int kk=0;kk<4;kk++){ \
        float a[4]; \
        int base = (wm*16 + g)*AS_STRIDE + kk*8 + q; \
        a[0]=A[base]; a[1]=A[base + 8*AS_STRIDE]; \
        a[2]=A[base+4]; a[3]=A[base + 8*AS_STRIDE + 4]; \
        _Pragma("unroll") \
        for (int j=0;j<12;j++){ \
            float b[2]; int bc = wn*96 + j*8 + g; \
            b[0]=Bb[(kk*8+q)*BS_STRIDE + bc]; \
            b[1]=Bb[(kk*8+q+4)*BS_STRIDE + bc]; \
            mma_tf32(acc[j], a, b, acc[j]); \
        } \
    } } while(0)

    QKV_LOAD(0);
    QKV_STORE(0);
    __syncthreads();

    #pragma unroll 1
    for (int c = 0; c < 32; c++){
        const int cur = c & 1;
        if (c < 31) QKV_LOAD((c+1) << 5);
        QKV_COMPUTE(cur);
        if (c < 31){
            QKV_STORE(cur ^ 1);
            __syncthreads();
        }
    }

    // epilogue: scatter to g_q/g_k/g_v; fold C^-0.5 into q
    #pragma unroll
    for (int j=0;j<12;j++){
        int n  = wn*96 + j*8 + q*2;
        int r0 = m0 + wm*16 + g;
        float sc   = (n < 64) ? 0.03125f : 1.f;
        float* dst = (n < 64) ? g_q : ((n < 128) ? g_k : g_v);
        int nn     = (n < 64) ? n   : ((n < 128) ? n-64 : n-128);
        *(float2*)&dst[(size_t)r0*H_ + nn]     = make_float2(acc[j][0]*sc, acc[j][1]*sc);
        *(float2*)&dst[(size_t)(r0+8)*H_ + nn] = make_float2(acc[j][2]*sc, acc[j][3]*sc);
    }
}

// ---------------------------------------------------------------------------
// Flash attention (causal), tf32 mma, cross-CTA split-K by 2.
// CTA: 128 threads, 64 query rows; blockIdx.z = key-tile parity.
// Writes unnormalized partials (O, m, l) to scratch; merge kernel combines.
// ---------------------------------------------------------------------------
#define PS_STRIDE 68
#define KS_STRIDE 68
#define VS_STRIDE 72
#define ATTN_SMEM ((64*PS_STRIDE + 64*KS_STRIDE + 64*VS_STRIDE)*4)  // 53248 B

__global__ __launch_bounds__(128) void attn_kernel()
{
    extern __shared__ float sm[];
    float* Qs = sm;                     // Q staging, then P
    float* Ks = sm + 64*PS_STRIDE;
    float* Vs = Ks + 64*KS_STRIDE;

    const int tid  = threadIdx.x;
    const int lane = tid & 31, w = tid >> 5;
    const int g = lane >> 2, q = lane & 3;
    const int qt = 31 - blockIdx.x;     // heavy blocks first
    const int b  = blockIdx.y;
    const int s  = blockIdx.z;          // key-tile parity
    const int q0 = qt * 64;

    const float* Qg = g_q + ((size_t)b*T_ + q0)*H_;
    const float* Kg = g_k + (size_t)b*T_*H_;
    const float* Vg = g_v + (size_t)b*T_*H_;

    // stage Q (tf32)
    #pragma unroll
    for (int it=0; it<8; it++){
        int i = tid + it*128;
        int r = i>>4, c4 = (i&15)*4;
        *(float4*)&Qs[r*PS_STRIDE + c4] = tf32r4(*(const float4*)&Qg[(size_t)r*H_ + c4]);
    }
    __syncthreads();

    // hoist Q fragments
    float qa[8][4];
    #pragma unroll
    for (int kk=0;kk<8;kk++){
        int base = (w*16+g)*PS_STRIDE + kk*8 + q;
        qa[kk][0]=Qs[base];
        qa[kk][1]=Qs[base + 8*PS_STRIDE];
        qa[kk][2]=Qs[base + 4];
        qa[kk][3]=Qs[base + 8*PS_STRIDE + 4];
    }
    __syncthreads();   // Qs now reusable as P

    float O[8][4];
    #pragma unroll
    for (int j=0;j<8;j++){O[j][0]=O[j][1]=O[j][2]=O[j][3]=0.f;}
    float m0r=-1e30f, m1r=-1e30f, l0=0.f, l1=0.f;

    #pragma unroll 1
    for (int jt = s; jt <= qt; jt += 2){
        __syncthreads();                 // Ks/Vs free, P consumed
        const int k0 = jt*64;
        #pragma unroll
        for (int it=0; it<8; it++){
            int i = tid + it*128;
            int r = i>>4, c4 = (i&15)*4;
            *(float4*)&Ks[r*KS_STRIDE + c4] = tf32r4(*(const float4*)&Kg[(size_t)(k0+r)*H_ + c4]);
            *(float4*)&Vs[r*VS_STRIDE + c4] = tf32r4(*(const float4*)&Vg[(size_t)(k0+r)*H_ + c4]);
        }
        __syncthreads();

        // S = Q K^T (scale pre-folded into q)
        float sreg[8][4];
        #pragma unroll
        for (int j=0;j<8;j++){sreg[j][0]=sreg[j][1]=sreg[j][2]=sreg[j][3]=0.f;}
        #pragma unroll
        for (int kk=0;kk<8;kk++){
            #pragma unroll
            for (int j=0;j<8;j++){
                float bb[2];
                int n = j*8 + g;
                bb[0]=Ks[n*KS_STRIDE + kk*8 + q];
                bb[1]=Ks[n*KS_STRIDE + kk*8 + q + 4];
                mma_tf32(sreg[j], qa[kk], bb, sreg[j]);
            }
        }

        if (jt == qt){   // diagonal tile → causal mask (tile-aligned)
            #pragma unroll
            for (int j=0;j<8;j++){
                int c0 = j*8 + 2*q, c1 = c0+1;
                int r0l = w*16+g, r1l = r0l+8;
                if (c0 > r0l) sreg[j][0] = -1e30f;
                if (c1 > r0l) sreg[j][1] = -1e30f;
                if (c0 > r1l) sreg[j][2] = -1e30f;
                if (c1 > r1l) sreg[j][3] = -1e30f;
            }
        }

        // online softmax (registers + quad shuffles)
        float mx0=-1e30f, mx1=-1e30f;
        #pragma unroll
        for (int j=0;j<8;j++){
            mx0 = fmaxf(mx0, fmaxf(sreg[j][0], sreg[j][1]));
            mx1 = fmaxf(mx1, fmaxf(sreg[j][2], sreg[j][3]));
        }
        mx0 = fmaxf(mx0, __shfl_xor_sync(0xffffffffu, mx0, 1));
        mx0 = fmaxf(mx0, __shfl_xor_sync(0xffffffffu, mx0, 2));
        mx1 = fmaxf(mx1, __shfl_xor_sync(0xffffffffu, mx1, 1));
        mx1 = fmaxf(mx1, __shfl_xor_sync(0xffffffffu, mx1, 2));

        float mn0 = fmaxf(m0r, mx0), mn1 = fmaxf(m1r, mx1);
        float al0 = __expf(m0r - mn0), al1 = __expf(m1r - mn1);
        m0r = mn0; m1r = mn1;
        l0 *= al0; l1 *= al1;

        float rs0=0.f, rs1=0.f;
        #pragma unroll
        for (int j=0;j<8;j++){
            float p0 = __expf(sreg[j][0]-mn0), p1 = __expf(sreg[j][1]-mn0);
            float p2 = __expf(sreg[j][2]-mn1), p3 = __expf(sreg[j][3]-mn1);
            rs0 += p0+p1; rs1 += p2+p3;
            O[j][0]*=al0; O[j][1]*=al0; O[j][2]*=al1; O[j][3]*=al1;
            int rbase = (w*16+g)*PS_STRIDE + j*8 + 2*q;
            *(float2*)&Qs[rbase]               = make_float2(tf32r(p0), tf32r(p1));
            *(float2*)&Qs[rbase + 8*PS_STRIDE] = make_float2(tf32r(p2), tf32r(p3));
        }
        rs0 += __shfl_xor_sync(0xffffffffu, rs0, 1);
        rs0 += __shfl_xor_sync(0xffffffffu, rs0, 2);
        rs1 += __shfl_xor_sync(0xffffffffu, rs1, 1);
        rs1 += __shfl_xor_sync(0xffffffffu, rs1, 2);
        l0 += rs0; l1 += rs1;

        __syncwarp();   // P rows are warp-private

        // O += P V
        #pragma unroll
        for (int kk=0;kk<8;kk++){
            float pa[4];
            int base = (w*16+g)*PS_STRIDE + kk*8 + q;
            pa[0]=Qs[base];
            pa[1]=Qs[base + 8*PS_STRIDE];
            pa[2]=Qs[base + 4];
            pa[3]=Qs[base + 8*PS_STRIDE + 4];
            #pragma unroll
            for (int j=0;j<8;j++){
                float bb[2];
                int hh = j*8 + g;
                bb[0]=Vs[(kk*8+q)*VS_STRIDE   + hh];
                bb[1]=Vs[(kk*8+q+4)*VS_STRIDE + hh];
                mma_tf32(O[j], pa, bb, O[j]);
            }
        }
    }

    // write unnormalized partials + (m, l)
    const size_t rg0 = (size_t)b*T_ + q0 + w*16 + g;   // rows rg0, rg0+8
    float* Po = g_po + (size_t)s*M_*H_ + rg0*H_;
    #pragma unroll
    for (int j=0;j<8;j++){
        *(float2*)&Po[j*8 + 2*q]        = make_float2(O[j][0], O[j][1]);
        *(float2*)&Po[8*H_ + j*8 + 2*q] = make_float2(O[j][2], O[j][3]);
    }
    if (q == 0){
        float* ml = g_ml + (size_t)s*M_*2;
        ml[rg0*2]       = m0r;  ml[rg0*2 + 1]       = l0;
        ml[(rg0+8)*2]   = m1r;  ml[(rg0+8)*2 + 1]   = l1;
    }
}

// ---------------------------------------------------------------------------
// Merge the two key-parity partials. One thread per output element.
// ---------------------------------------------------------------------------
__global__ __launch_bounds__(256) void merge_kernel(float* __restrict__ out)
{
    const int idx = blockIdx.x*256 + threadIdx.x;   // [0, M_*H_)
    const int row = idx >> 6;
    float ma = g_ml[row*2],          la = g_ml[row*2 + 1];
    float mb = g_ml[M_*2 + row*2],   lb = g_ml[M_*2 + row*2 + 1];
    float M  = fmaxf(ma, mb);
    float ea = __expf(ma - M), eb = __expf(mb - M);
    float inv = 1.f / (la*ea + lb*eb);
    out[idx] = (g_po[idx]*ea + g_po[M_*H_ + idx]*eb) * inv;
}

extern "C" void kernel_launch(void* const* d_in, const int* in_sizes, int n_in,
                              void* d_out, int out_size)
{
    const float* x  = (const float*)d_in[0];
    const float* wq = (const float*)d_in[1];
    const float* wk = (const float*)d_in[2];
    const float* wv = (const float*)d_in[3];
    float* out = (float*)d_out;

    cudaFuncSetAttribute(qkv_kernel,
                         cudaFuncAttributeMaxDynamicSharedMemorySize, QKV_SMEM);
    cudaFuncSetAttribute(attn_kernel,
                         cudaFuncAttributeMaxDynamicSharedMemorySize, ATTN_SMEM);

    qkv_kernel<<<M_/64, 256, QKV_SMEM>>>(x, wq, wk, wv);
    dim3 grid(T_/64, B_, 2);
    attn_kernel<<<grid, 128, ATTN_SMEM>>>();
    merge_kernel<<<(M_*H_)/256, 256>>>(out);
}